// round 4
// baseline (speedup 1.0000x reference)
#include <cuda_runtime.h>
#include <cuda_bf16.h>
#include <cstdint>

// ============================ problem constants ============================
#define NROWS   8192
#define DDIM    128
#define NVIEWS  3
#define TILE    128
#define NT      (NROWS / TILE)        // 64 n-tiles
#define NCHUNK  2                     // m-range split per n-tile -> 128 CTAs
#define TPC     (NT / NCHUNK)         // 32 m-tiles per CTA

// SMEM layout
#define APITCH  272                   // bytes per row of A/B tiles (136 bf16) — ldmatrix conflict-free
#define SPITCHF 132                   // floats per row of S tile
#define SPITCHB 528                   // bytes per row of S tile (33 x 16B, cp.async aligned)
#define SM_A    0
#define SM_B    (TILE * APITCH)               // 34816
#define SM_S    (SM_B + TILE * APITCH)        // 69632
#define SBUF    (TILE * SPITCHB)              // 67584 per S buffer (x2)
#define SMEM_BYTES (SM_S + 2 * SBUF)          // 204800

// ============================ device scratch ===============================
__device__ __nv_bfloat16 g_A[NROWS * DDIM];                 // normalized Hc (bf16)
__device__ __nv_bfloat16 g_B[NVIEWS * NROWS * DDIM];        // normalized Hv (bf16)
__device__ float g_partial[4 * NVIEWS * NROWS];             // [chunk*2+warp_m][v][n]
__device__ float g_loss[NVIEWS * NROWS];

// ============================ ptx helpers (baseline PTX only) ==============
__device__ __forceinline__ uint32_t smem_u32(const void* p) {
    uint32_t a;
    asm("{ .reg .u64 t; cvta.to.shared.u64 t, %1; cvt.u32.u64 %0, t; }"
        : "=r"(a) : "l"(p));
    return a;
}

__device__ __forceinline__ void cp_async16(uint32_t dst, const void* src) {
    asm volatile("cp.async.cg.shared.global [%0], [%1], 16;"
                 :: "r"(dst), "l"(src) : "memory");
}
#define CP_COMMIT() asm volatile("cp.async.commit_group;" ::: "memory")
#define CP_WAIT(n)  asm volatile("cp.async.wait_group %0;" :: "n"(n) : "memory")

__device__ __forceinline__ void ldmatrix_x4(uint32_t* r, uint32_t addr) {
    asm volatile("ldmatrix.sync.aligned.m8n8.x4.shared.b16 {%0,%1,%2,%3}, [%4];"
                 : "=r"(r[0]), "=r"(r[1]), "=r"(r[2]), "=r"(r[3]) : "r"(addr));
}

__device__ __forceinline__ void mma_16816(float* d, const uint32_t* a,
                                          uint32_t b0, uint32_t b1) {
    asm volatile(
        "mma.sync.aligned.m16n8k16.row.col.f32.bf16.bf16.f32 "
        "{%0,%1,%2,%3}, {%4,%5,%6,%7}, {%8,%9}, {%0,%1,%2,%3};"
        : "+f"(d[0]), "+f"(d[1]), "+f"(d[2]), "+f"(d[3])
        : "r"(a[0]), "r"(a[1]), "r"(a[2]), "r"(a[3]), "r"(b0), "r"(b1));
}

// ============================ kernel 1: normalize ==========================
__global__ __launch_bounds__(256) void normalize_kernel(
    const float* __restrict__ Hc, const float* __restrict__ Hv) {
    int w = (blockIdx.x * blockDim.x + threadIdx.x) >> 5;   // one warp per row
    int lane = threadIdx.x & 31;
    if (w >= 4 * NROWS) return;
    const float* src;
    __nv_bfloat16* dst;
    if (w < NROWS) { src = Hc + (size_t)w * DDIM;              dst = g_A + (size_t)w * DDIM; }
    else { size_t r = (size_t)(w - NROWS); src = Hv + r * DDIM; dst = g_B + r * DDIM; }

    float4 x = ((const float4*)src)[lane];
    float s = x.x * x.x + x.y * x.y + x.z * x.z + x.w * x.w;
#pragma unroll
    for (int o = 16; o; o >>= 1) s += __shfl_xor_sync(0xFFFFFFFFu, s, o);
    float inv = 1.0f / fmaxf(sqrtf(s), 1e-12f);

    __nv_bfloat162 lo = __floats2bfloat162_rn(x.x * inv, x.y * inv);
    __nv_bfloat162 hi = __floats2bfloat162_rn(x.z * inv, x.w * inv);
    uint2 pk;
    pk.x = *(uint32_t*)&lo;
    pk.y = *(uint32_t*)&hi;
    ((uint2*)dst)[lane] = pk;
}

// ============================ kernel 2: fused GEMM + weighted-exp denoms ===
// CTA: 256 threads = 8 warps as 4(n) x 2(m). Output tile 128n x 128m.
// Warp tile: 32n x 64m -> acc[2 nfrag][8 mtile][4] fp32 in registers.
__global__ __launch_bounds__(256, 1) void sgcl_main(const float* __restrict__ S) {
    extern __shared__ __align__(1024) char smem[];
    const uint32_t sbase = smem_u32(smem);
    const int tid = threadIdx.x, lane = tid & 31, wid = tid >> 5;
    const int warp_n = wid & 3, warp_m = wid >> 2;
    const int chunk = blockIdx.x;
    const int n0 = blockIdx.y * TILE;
    const int m_base = chunk * TPC * TILE;

    // ---- prefetch S tile 0 into buffer 0 (cp.async) ----
    {
        const float* src = S + (size_t)n0 * NROWS + m_base;
        uint32_t dstb = sbase + SM_S;
#pragma unroll
        for (int t = 0; t < 16; t++) {
            int i = tid + t * 256;                  // 4096 x 16B chunks
            int row = i >> 5, c = i & 31;
            cp_async16(dstb + row * SPITCHB + c * 16,
                       src + (size_t)row * NROWS + c * 4);
        }
        CP_COMMIT();
    }

    // ---- stage A tile (once) ----
    {
        const uint4* src = (const uint4*)(g_A + (size_t)n0 * DDIM);
#pragma unroll
        for (int t = 0; t < 8; t++) {
            int i = tid + t * 256;                  // 2048 x 16B
            int row = i >> 4, c = i & 15;
            *(uint4*)(smem + SM_A + row * APITCH + c * 16) = src[i];
        }
    }

    // ---- per-lane ldmatrix base addresses ----
    uint32_t aBase[2], bBase[4];
#pragma unroll
    for (int fi = 0; fi < 2; fi++)
        aBase[fi] = sbase + SM_A +
                    (uint32_t)(warp_n * 32 + fi * 16 + (lane & 15)) * APITCH +
                    (uint32_t)(lane >> 4) * 16;
#pragma unroll
    for (int bp = 0; bp < 4; bp++)
        bBase[bp] = sbase + SM_B +
                    (uint32_t)(warp_m * 64 + bp * 16 + ((lane >> 4) << 3) + (lane & 7)) * APITCH +
                    (uint32_t)((lane >> 3) & 1) * 16;

    float accv[NVIEWS][4];
#pragma unroll
    for (int v = 0; v < NVIEWS; v++)
#pragma unroll
        for (int r = 0; r < 4; r++) accv[v][r] = 0.0f;

    for (int mt = 0; mt < TPC; mt++) {
        const int m0 = m_base + mt * TILE;
        __syncthreads();   // prev epilogue done: S buffer (mt+1)&1 safe to refill

        if (mt + 1 < TPC) {      // prefetch next S tile
            const float* src = S + (size_t)n0 * NROWS + (m0 + TILE);
            uint32_t dstb = sbase + SM_S + (uint32_t)((mt + 1) & 1) * SBUF;
#pragma unroll
            for (int t = 0; t < 16; t++) {
                int i = tid + t * 256;
                int row = i >> 5, c = i & 31;
                cp_async16(dstb + row * SPITCHB + c * 16,
                           src + (size_t)row * NROWS + c * 4);
            }
            CP_COMMIT();
        }
        const float* sS = (const float*)(smem + SM_S + (size_t)(mt & 1) * SBUF);

#pragma unroll
        for (int v = 0; v < NVIEWS; v++) {
            if (v) __syncthreads();       // prev view's mma reads of smB done
            // stage B tile for this view
            {
                const uint4* src = (const uint4*)(g_B + ((size_t)v * NROWS + m0) * DDIM);
#pragma unroll
                for (int t = 0; t < 8; t++) {
                    int i = tid + t * 256;
                    int row = i >> 4, c = i & 15;
                    *(uint4*)(smem + SM_B + row * APITCH + c * 16) = src[i];
                }
            }
            if (v == 0) { if (mt + 1 < TPC) CP_WAIT(1); else CP_WAIT(0); }
            __syncthreads();

            // ---- 128x128x128 bf16 GEMM (register accumulators) ----
            float acc[2][8][4];
#pragma unroll
            for (int fi = 0; fi < 2; fi++)
#pragma unroll
                for (int mi = 0; mi < 8; mi++)
#pragma unroll
                    for (int r = 0; r < 4; r++) acc[fi][mi][r] = 0.0f;

#pragma unroll
            for (int ks = 0; ks < 8; ks++) {
                uint32_t a[2][4], b[4][4];
                ldmatrix_x4(a[0], aBase[0] + ks * 32);
                ldmatrix_x4(a[1], aBase[1] + ks * 32);
#pragma unroll
                for (int bp = 0; bp < 4; bp++)
                    ldmatrix_x4(b[bp], bBase[bp] + ks * 32);
#pragma unroll
                for (int fi = 0; fi < 2; fi++)
#pragma unroll
                    for (int bp = 0; bp < 4; bp++)
#pragma unroll
                        for (int t2 = 0; t2 < 2; t2++)
                            mma_16816(acc[fi][bp * 2 + t2], a[fi],
                                      b[bp][2 * t2], b[bp][2 * t2 + 1]);
            }

            // ---- fused epilogue: accv += (1 - S) * exp(sim / 0.5) ----
#pragma unroll
            for (int fi = 0; fi < 2; fi++) {
                const float* pA = sS +
                    (size_t)(warp_n * 32 + fi * 16 + (lane >> 2)) * SPITCHF +
                    warp_m * 64 + 2 * (lane & 3);
                const float* pB = pA + 8 * SPITCHF;
                float sA = 0.0f, sB = 0.0f;
#pragma unroll
                for (int mi = 0; mi < 8; mi++) {
                    float2 wA = *(const float2*)(pA + mi * 8);
                    float2 wB = *(const float2*)(pB + mi * 8);
                    const float* d = acc[fi][mi];
                    sA += (1.0f - wA.x) * __expf(2.0f * d[0]) +
                          (1.0f - wA.y) * __expf(2.0f * d[1]);
                    sB += (1.0f - wB.x) * __expf(2.0f * d[2]) +
                          (1.0f - wB.y) * __expf(2.0f * d[3]);
                }
                accv[v][fi * 2 + 0] += sA;
                accv[v][fi * 2 + 1] += sB;
            }
        }
    }

    // ---- quad-reduce and write partial denominators ----
#pragma unroll
    for (int v = 0; v < NVIEWS; v++)
#pragma unroll
        for (int r = 0; r < 4; r++) {
            float val = accv[v][r];
            val += __shfl_xor_sync(0xFFFFFFFFu, val, 1);
            val += __shfl_xor_sync(0xFFFFFFFFu, val, 2);
            if ((lane & 3) == 0) {
                int nl = warp_n * 32 + (r >> 1) * 16 + (lane >> 2) + (r & 1) * 8;
                g_partial[((chunk * 2 + warp_m) * NVIEWS + v) * NROWS + n0 + nl] = val;
            }
        }
}

// ============================ kernel 3: positive + per-item loss ===========
__global__ __launch_bounds__(256) void posloss_kernel() {
    int w = (blockIdx.x * blockDim.x + threadIdx.x) >> 5;  // one warp per (v, n)
    if (w >= NVIEWS * NROWS) return;
    int lane = threadIdx.x & 31;
    int v = w / NROWS, n = w % NROWS;

    const __nv_bfloat162* pa = (const __nv_bfloat162*)(g_A + (size_t)n * DDIM) + lane * 2;
    const __nv_bfloat162* pb =
        (const __nv_bfloat162*)(g_B + ((size_t)v * NROWS + n) * DDIM) + lane * 2;
    float d = 0.f;
#pragma unroll
    for (int i = 0; i < 2; i++) {
        float2 a = __bfloat1622float2(pa[i]);
        float2 b = __bfloat1622float2(pb[i]);
        d += a.x * b.x + a.y * b.y;
    }
#pragma unroll
    for (int o = 16; o; o >>= 1) d += __shfl_xor_sync(0xFFFFFFFFu, d, o);

    if (lane == 0) {
        float denom = 0.f;
#pragma unroll
        for (int p = 0; p < 4; p++)
            denom += g_partial[(p * NVIEWS + v) * NROWS + n];
        denom = fmaxf(denom, 1e-9f);
        g_loss[w] = logf(denom) - 2.0f * d;   // -(pos - log denom)
    }
}

// ============================ kernel 4: deterministic reduce ===============
__global__ __launch_bounds__(1024) void reduce_kernel(float* __restrict__ out) {
    __shared__ float sm[1024];
    float s = 0.f;
    for (int i = threadIdx.x; i < NVIEWS * NROWS; i += 1024) s += g_loss[i];
    sm[threadIdx.x] = s;
    __syncthreads();
#pragma unroll
    for (int st = 512; st; st >>= 1) {
        if (threadIdx.x < st) sm[threadIdx.x] += sm[threadIdx.x + st];
        __syncthreads();
    }
    if (threadIdx.x == 0) out[0] = sm[0] * (1.0f / (NVIEWS * NROWS));
}

// ============================ launch =======================================
extern "C" void kernel_launch(void* const* d_in, const int* in_sizes, int n_in,
                              void* d_out, int out_size) {
    const float* Hc = (const float*)d_in[0];
    const float* S  = (const float*)d_in[1];
    const float* Hv = (const float*)d_in[2];

    cudaFuncSetAttribute(sgcl_main, cudaFuncAttributeMaxDynamicSharedMemorySize,
                         SMEM_BYTES);

    normalize_kernel<<<(4 * NROWS) / 8, 256>>>(Hc, Hv);
    sgcl_main<<<dim3(NCHUNK, NT), 256, SMEM_BYTES>>>(S);
    posloss_kernel<<<(NVIEWS * NROWS) / 8, 256>>>();
    reduce_kernel<<<1, 1024>>>((float*)d_out);
}

// round 6
// speedup vs baseline: 1.2005x; 1.2005x over previous
#include <cuda_runtime.h>
#include <cuda_bf16.h>
#include <cstdint>

// ============================ problem constants ============================
#define NROWS   8192
#define DDIM    128
#define NVIEWS  3
#define TILE_N  128
#define TILE_M  64
#define NCHUNK  2                       // m-range split -> grid 2 x 64 = 128 CTAs
#define TPC     (NROWS / NCHUNK / TILE_M)   // 64 m-tiles per CTA

// SMEM layout
#define APITCH  272                     // bytes/row A,B tiles (136 bf16)
#define SPITCHW 72                      // S pitch in floats (conflict-free epilogue)
#define SPITCHB (SPITCHW * 4)           // 288 B
#define SM_A    0
#define A_BYTES (TILE_N * APITCH)               // 34816
#define SM_B    A_BYTES
#define BVIEW   (TILE_M * APITCH)               // 17408 per view
#define SM_S    (SM_B + NVIEWS * BVIEW)         // 87040
#define SBUF    (TILE_N * SPITCHB)              // 36864 per buffer
#define SMEM_BYTES (SM_S + 2 * SBUF)            // 160768

// ============================ device scratch ===============================
__device__ __nv_bfloat16 g_A[NROWS * DDIM];
__device__ __nv_bfloat16 g_B[NVIEWS * NROWS * DDIM];
__device__ float g_partial[4 * NVIEWS * NROWS];   // [chunk*2+warp_m][v][n]
__device__ float g_bsum[96];

// ============================ ptx helpers ==================================
__device__ __forceinline__ uint32_t smem_u32(const void* p) {
    uint32_t a;
    asm("{ .reg .u64 t; cvta.to.shared.u64 t, %1; cvt.u32.u64 %0, t; }"
        : "=r"(a) : "l"(p));
    return a;
}

__device__ __forceinline__ void cp_async16(uint32_t dst, const void* src) {
    asm volatile("cp.async.cg.shared.global [%0], [%1], 16;"
                 :: "r"(dst), "l"(src) : "memory");
}
#define CP_COMMIT() asm volatile("cp.async.commit_group;" ::: "memory")
#define CP_WAIT(n)  asm volatile("cp.async.wait_group %0;" :: "n"(n) : "memory")

__device__ __forceinline__ void ldmatrix_x4(uint32_t* r, uint32_t addr) {
    asm volatile("ldmatrix.sync.aligned.m8n8.x4.shared.b16 {%0,%1,%2,%3}, [%4];"
                 : "=r"(r[0]), "=r"(r[1]), "=r"(r[2]), "=r"(r[3]) : "r"(addr));
}

__device__ __forceinline__ void mma_16816(float* d, const uint32_t* a,
                                          uint32_t b0, uint32_t b1) {
    asm volatile(
        "mma.sync.aligned.m16n8k16.row.col.f32.bf16.bf16.f32 "
        "{%0,%1,%2,%3}, {%4,%5,%6,%7}, {%8,%9}, {%0,%1,%2,%3};"
        : "+f"(d[0]), "+f"(d[1]), "+f"(d[2]), "+f"(d[3])
        : "r"(a[0]), "r"(a[1]), "r"(a[2]), "r"(a[3]), "r"(b0), "r"(b1));
}

// ============================ kernel 1: normalize ==========================
__global__ __launch_bounds__(256) void normalize_kernel(
    const float* __restrict__ Hc, const float* __restrict__ Hv) {
    int w = (blockIdx.x * blockDim.x + threadIdx.x) >> 5;   // one warp per row
    int lane = threadIdx.x & 31;
    if (w >= 4 * NROWS) return;
    const float* src;
    __nv_bfloat16* dst;
    if (w < NROWS) { src = Hc + (size_t)w * DDIM;              dst = g_A + (size_t)w * DDIM; }
    else { size_t r = (size_t)(w - NROWS); src = Hv + r * DDIM; dst = g_B + r * DDIM; }

    float4 x = ((const float4*)src)[lane];
    float s = x.x * x.x + x.y * x.y + x.z * x.z + x.w * x.w;
#pragma unroll
    for (int o = 16; o; o >>= 1) s += __shfl_xor_sync(0xFFFFFFFFu, s, o);
    float inv = 1.0f / fmaxf(sqrtf(s), 1e-12f);

    __nv_bfloat162 lo = __floats2bfloat162_rn(x.x * inv, x.y * inv);
    __nv_bfloat162 hi = __floats2bfloat162_rn(x.z * inv, x.w * inv);
    uint2 pk;
    pk.x = *(uint32_t*)&lo;
    pk.y = *(uint32_t*)&hi;
    ((uint2*)dst)[lane] = pk;
}

// ============================ kernel 2: fused GEMM + weighted-exp denoms ===
// CTA 256 thr = 8 warps (4n x 2m). Output tile 128n x 64m, 3 views resident.
// Only 2 syncs per m-tile; warps free-run across the 3 views so tensor (HMMA)
// and MUFU (exp) pipes overlap across the 2 warps per SMSP.
__global__ __launch_bounds__(256, 1) void sgcl_main(const float* __restrict__ S) {
    extern __shared__ __align__(1024) char smem[];
    const uint32_t sbase = smem_u32(smem);
    const int tid = threadIdx.x, lane = tid & 31, wid = tid >> 5;
    const int warp_n = wid & 3, warp_m = wid >> 2;
    const int chunk = blockIdx.x;
    const int n0 = blockIdx.y * TILE_N;
    const int m_base = chunk * TPC * TILE_M;

    // ---- prefetch S tile 0 ----
    {
        const float* src = S + (size_t)n0 * NROWS + m_base;
#pragma unroll
        for (int t = 0; t < 8; t++) {
            int i = tid + t * 256;                 // 2048 x 16B
            int row = i >> 4, c = i & 15;
            cp_async16(sbase + SM_S + row * SPITCHB + c * 16,
                       src + (size_t)row * NROWS + c * 4);
        }
        CP_COMMIT();
    }

    // ---- stage A tile (once) ----
    {
        const uint4* src = (const uint4*)(g_A + (size_t)n0 * DDIM);
#pragma unroll
        for (int t = 0; t < 8; t++) {
            int i = tid + t * 256;                 // 2048 x 16B
            int row = i >> 4, c = i & 15;
            *(uint4*)(smem + SM_A + row * APITCH + c * 16) = src[i];
        }
    }
    __syncthreads();

    // ---- hoist A fragments to registers (loop-invariant for whole CTA) ----
    uint32_t a_frag[8][2][4];
    {
        uint32_t aBase0 = sbase + SM_A +
            (uint32_t)(warp_n * 32 + (lane & 15)) * APITCH + (uint32_t)(lane >> 4) * 16;
#pragma unroll
        for (int ks = 0; ks < 8; ks++) {
            ldmatrix_x4(a_frag[ks][0], aBase0 + ks * 32);
            ldmatrix_x4(a_frag[ks][1], aBase0 + 16 * APITCH + ks * 32);
        }
    }

    // B ldmatrix per-lane base (view 0; other views add v*BVIEW)
    const uint32_t bBase0 = sbase + SM_B +
        (uint32_t)(warp_m * 32 + ((lane >> 4) << 3) + (lane & 7)) * APITCH +
        (uint32_t)((lane >> 3) & 1) * 16;

    float accv[NVIEWS][4];
#pragma unroll
    for (int v = 0; v < NVIEWS; v++)
#pragma unroll
        for (int r = 0; r < 4; r++) accv[v][r] = 0.0f;

    for (int mt = 0; mt < TPC; mt++) {
        const int m0 = m_base + mt * TILE_M;
        __syncthreads();   // all warps done with tile mt-1 (B + both S buffers safe)

        if (mt + 1 < TPC) {    // prefetch next S tile
            const float* src = S + (size_t)n0 * NROWS + (m0 + TILE_M);
            uint32_t dstb = sbase + SM_S + (uint32_t)((mt + 1) & 1) * SBUF;
#pragma unroll
            for (int t = 0; t < 8; t++) {
                int i = tid + t * 256;
                int row = i >> 4, c = i & 15;
                cp_async16(dstb + row * SPITCHB + c * 16,
                           src + (size_t)row * NROWS + c * 4);
            }
            CP_COMMIT();
        }

        // stage B tiles for ALL 3 views (64 rows x 128 bf16 each)
        {
#pragma unroll
            for (int t = 0; t < 12; t++) {
                int i = tid + t * 256;             // 3072 x 16B
                int view = i >> 10, r = (i >> 4) & 63, c = i & 15;
                const uint4* src = (const uint4*)(g_B +
                    ((size_t)view * NROWS + m0 + r) * DDIM);
                *(uint4*)(smem + SM_B + view * BVIEW + r * APITCH + c * 16) = src[c];
            }
        }
        if (mt + 1 < TPC) CP_WAIT(1); else CP_WAIT(0);
        __syncthreads();   // B staged + S(mt) visible

        const float* sS = (const float*)(smem + SM_S + (size_t)(mt & 1) * SBUF);

#pragma unroll
        for (int v = 0; v < NVIEWS; v++) {
            // ---- 128x64x128 bf16 GEMM, register accumulators ----
            float acc[2][4][4];
#pragma unroll
            for (int fi = 0; fi < 2; fi++)
#pragma unroll
                for (int mi = 0; mi < 4; mi++)
#pragma unroll
                    for (int r = 0; r < 4; r++) acc[fi][mi][r] = 0.0f;

            const uint32_t bV = bBase0 + (uint32_t)v * BVIEW;
#pragma unroll
            for (int ks = 0; ks < 8; ks++) {
                uint32_t b[2][4];
                ldmatrix_x4(b[0], bV + ks * 32);
                ldmatrix_x4(b[1], bV + 16 * APITCH + ks * 32);
#pragma unroll
                for (int fi = 0; fi < 2; fi++)
#pragma unroll
                    for (int bp = 0; bp < 2; bp++)
#pragma unroll
                        for (int t2 = 0; t2 < 2; t2++)
                            mma_16816(acc[fi][bp * 2 + t2], a_frag[ks][fi],
                                      b[bp][2 * t2], b[bp][2 * t2 + 1]);
            }

            // ---- fused epilogue: accv += (1 - S) * exp(sim / 0.5) ----
#pragma unroll
            for (int fi = 0; fi < 2; fi++) {
                const float* pA = sS +
                    (size_t)(warp_n * 32 + fi * 16 + (lane >> 2)) * SPITCHW +
                    warp_m * 32 + 2 * (lane & 3);
                const float* pB = pA + 8 * SPITCHW;
                float sA = 0.0f, sB = 0.0f;
#pragma unroll
                for (int mi = 0; mi < 4; mi++) {
                    float2 wA = *(const float2*)(pA + mi * 8);
                    float2 wB = *(const float2*)(pB + mi * 8);
                    const float* d = acc[fi][mi];
                    sA += (1.0f - wA.x) * __expf(2.0f * d[0]) +
                          (1.0f - wA.y) * __expf(2.0f * d[1]);
                    sB += (1.0f - wB.x) * __expf(2.0f * d[2]) +
                          (1.0f - wB.y) * __expf(2.0f * d[3]);
                }
                accv[v][fi * 2 + 0] += sA;
                accv[v][fi * 2 + 1] += sB;
            }
        }
    }

    // ---- quad-reduce, write partial denominators ----
#pragma unroll
    for (int v = 0; v < NVIEWS; v++)
#pragma unroll
        for (int r = 0; r < 4; r++) {
            float val = accv[v][r];
            val += __shfl_xor_sync(0xFFFFFFFFu, val, 1);
            val += __shfl_xor_sync(0xFFFFFFFFu, val, 2);
            if ((lane & 3) == 0) {
                int nl = warp_n * 32 + (r >> 1) * 16 + (lane >> 2) + (r & 1) * 8;
                g_partial[((chunk * 2 + warp_m) * NVIEWS + v) * NROWS + n0 + nl] = val;
            }
        }
}

// ============================ kernel 3: positive + loss + block partials ===
// 96 blocks x 256 threads; thread = one (v, n). Block partial -> g_bsum.
__global__ __launch_bounds__(256) void posloss_kernel() {
    __shared__ float sm[256];
    int idx = blockIdx.x * 256 + threadIdx.x;      // < 24576
    int v = idx / NROWS, n = idx % NROWS;

    const uint4* pa = (const uint4*)(g_A + (size_t)n * DDIM);
    const uint4* pb = (const uint4*)(g_B + ((size_t)v * NROWS + n) * DDIM);
    float d = 0.f;
#pragma unroll
    for (int i = 0; i < 16; i++) {
        uint4 ua = pa[i], ub = pb[i];
        const __nv_bfloat162* xa = (const __nv_bfloat162*)&ua;
        const __nv_bfloat162* xb = (const __nv_bfloat162*)&ub;
#pragma unroll
        for (int j = 0; j < 4; j++) {
            float2 a = __bfloat1622float2(xa[j]);
            float2 b = __bfloat1622float2(xb[j]);
            d += a.x * b.x + a.y * b.y;
        }
    }
    float denom = 0.f;
#pragma unroll
    for (int p = 0; p < 4; p++)
        denom += g_partial[(p * NVIEWS + v) * NROWS + n];
    denom = fmaxf(denom, 1e-9f);
    float loss = logf(denom) - 2.0f * d;           // -(pos - log denom)

    sm[threadIdx.x] = loss;
    __syncthreads();
#pragma unroll
    for (int st = 128; st; st >>= 1) {
        if (threadIdx.x < st) sm[threadIdx.x] += sm[threadIdx.x + st];
        __syncthreads();
    }
    if (threadIdx.x == 0) g_bsum[blockIdx.x] = sm[0];
}

// ============================ kernel 4: final tiny reduce ==================
__global__ void final_reduce(float* __restrict__ out) {
    int lane = threadIdx.x;
    float s = 0.f;
    for (int i = lane; i < 96; i += 32) s += g_bsum[i];
#pragma unroll
    for (int o = 16; o; o >>= 1) s += __shfl_xor_sync(0xFFFFFFFFu, s, o);
    if (lane == 0) out[0] = s * (1.0f / (NVIEWS * NROWS));
}

// ============================ launch =======================================
extern "C" void kernel_launch(void* const* d_in, const int* in_sizes, int n_in,
                              void* d_out, int out_size) {
    const float* Hc = (const float*)d_in[0];
    const float* S  = (const float*)d_in[1];
    const float* Hv = (const float*)d_in[2];

    cudaFuncSetAttribute(sgcl_main, cudaFuncAttributeMaxDynamicSharedMemorySize,
                         SMEM_BYTES);

    normalize_kernel<<<(4 * NROWS) / 8, 256>>>(Hc, Hv);
    sgcl_main<<<dim3(NCHUNK, NROWS / TILE_N), 256, SMEM_BYTES>>>(S);
    posloss_kernel<<<96, 256>>>();
    final_reduce<<<1, 32>>>((float*)d_out);
}

// round 7
// speedup vs baseline: 1.3482x; 1.1230x over previous
#include <cuda_runtime.h>
#include <cuda_bf16.h>
#include <cstdint>

// ============================ problem constants ============================
#define NROWS   8192
#define DDIM    128
#define NVIEWS  3
#define TILE_N  128
#define TILE_M  64
#define NCHUNK  16                      // m-range split -> grid 16 x 64 = 1024 CTAs
#define TPC     (NROWS / NCHUNK / TILE_M)   // 8 m-tiles per CTA
#define NSLOT   (NCHUNK * 2)            // partial-denom slots (chunk x warp_m)

// SMEM layout
#define APITCH  272                     // bytes/row A,B tiles (136 bf16)
#define SPITCHW 72                      // S pitch in floats (conflict-free epilogue)
#define SPITCHB (SPITCHW * 4)           // 288 B
#define SM_A    0
#define A_BYTES (TILE_N * APITCH)               // 34816
#define SM_B    A_BYTES
#define BVIEW   (TILE_M * APITCH)               // 17408 per view
#define SM_S    (SM_B + NVIEWS * BVIEW)         // 87040
#define SBUF    (TILE_N * SPITCHB)              // 36864 per buffer
#define SMEM_BYTES (SM_S + 2 * SBUF)            // 160768

// ============================ device scratch ===============================
__device__ __nv_bfloat16 g_A[NROWS * DDIM];
__device__ __nv_bfloat16 g_B[NVIEWS * NROWS * DDIM];
__device__ float g_partial[NSLOT * NVIEWS * NROWS];   // [slot][v][n]
__device__ float g_bsum[96];

// ============================ ptx helpers ==================================
__device__ __forceinline__ uint32_t smem_u32(const void* p) {
    uint32_t a;
    asm("{ .reg .u64 t; cvta.to.shared.u64 t, %1; cvt.u32.u64 %0, t; }"
        : "=r"(a) : "l"(p));
    return a;
}

__device__ __forceinline__ void cp_async16(uint32_t dst, const void* src) {
    asm volatile("cp.async.cg.shared.global [%0], [%1], 16;"
                 :: "r"(dst), "l"(src) : "memory");
}
#define CP_COMMIT() asm volatile("cp.async.commit_group;" ::: "memory")
#define CP_WAIT(n)  asm volatile("cp.async.wait_group %0;" :: "n"(n) : "memory")

__device__ __forceinline__ void ldmatrix_x4(uint32_t* r, uint32_t addr) {
    asm volatile("ldmatrix.sync.aligned.m8n8.x4.shared.b16 {%0,%1,%2,%3}, [%4];"
                 : "=r"(r[0]), "=r"(r[1]), "=r"(r[2]), "=r"(r[3]) : "r"(addr));
}

__device__ __forceinline__ void mma_16816(float* d, const uint32_t* a,
                                          uint32_t b0, uint32_t b1) {
    asm volatile(
        "mma.sync.aligned.m16n8k16.row.col.f32.bf16.bf16.f32 "
        "{%0,%1,%2,%3}, {%4,%5,%6,%7}, {%8,%9}, {%0,%1,%2,%3};"
        : "+f"(d[0]), "+f"(d[1]), "+f"(d[2]), "+f"(d[3])
        : "r"(a[0]), "r"(a[1]), "r"(a[2]), "r"(a[3]), "r"(b0), "r"(b1));
}

// ===== tiny pad kernels (align ncu -s 5 onto sgcl_main; removable) =========
__global__ void prof_pad1() { if (blockIdx.x == 1) g_bsum[0] = 0.f; }
__global__ void prof_pad2() { if (blockIdx.x == 1) g_bsum[1] = 0.f; }

// ============================ kernel 1: normalize ==========================
__global__ __launch_bounds__(256) void normalize_kernel(
    const float* __restrict__ Hc, const float* __restrict__ Hv) {
    int w = (blockIdx.x * blockDim.x + threadIdx.x) >> 5;   // one warp per row
    int lane = threadIdx.x & 31;
    if (w >= 4 * NROWS) return;
    const float* src;
    __nv_bfloat16* dst;
    if (w < NROWS) { src = Hc + (size_t)w * DDIM;              dst = g_A + (size_t)w * DDIM; }
    else { size_t r = (size_t)(w - NROWS); src = Hv + r * DDIM; dst = g_B + r * DDIM; }

    float4 x = ((const float4*)src)[lane];
    float s = x.x * x.x + x.y * x.y + x.z * x.z + x.w * x.w;
#pragma unroll
    for (int o = 16; o; o >>= 1) s += __shfl_xor_sync(0xFFFFFFFFu, s, o);
    float inv = 1.0f / fmaxf(sqrtf(s), 1e-12f);

    __nv_bfloat162 lo = __floats2bfloat162_rn(x.x * inv, x.y * inv);
    __nv_bfloat162 hi = __floats2bfloat162_rn(x.z * inv, x.w * inv);
    uint2 pk;
    pk.x = *(uint32_t*)&lo;
    pk.y = *(uint32_t*)&hi;
    ((uint2*)dst)[lane] = pk;
}

// ============================ kernel 2: fused GEMM + weighted-exp denoms ===
// Grid 16 x 64 = 1024 CTAs (~7 short waves -> all 148 SMs busy).
// CTA 256 thr = 8 warps (4n x 2m). Output tile 128n x 64m, 3 views resident.
__global__ __launch_bounds__(256, 1) void sgcl_main(const float* __restrict__ S) {
    extern __shared__ __align__(1024) char smem[];
    const uint32_t sbase = smem_u32(smem);
    const int tid = threadIdx.x, lane = tid & 31, wid = tid >> 5;
    const int warp_n = wid & 3, warp_m = wid >> 2;
    const int chunk = blockIdx.x;
    const int n0 = blockIdx.y * TILE_N;
    const int m_base = chunk * TPC * TILE_M;

    // ---- prefetch S tile 0 ----
    {
        const float* src = S + (size_t)n0 * NROWS + m_base;
#pragma unroll
        for (int t = 0; t < 8; t++) {
            int i = tid + t * 256;                 // 2048 x 16B
            int row = i >> 4, c = i & 15;
            cp_async16(sbase + SM_S + row * SPITCHB + c * 16,
                       src + (size_t)row * NROWS + c * 4);
        }
        CP_COMMIT();
    }

    // ---- stage A tile (once) ----
    {
        const uint4* src = (const uint4*)(g_A + (size_t)n0 * DDIM);
#pragma unroll
        for (int t = 0; t < 8; t++) {
            int i = tid + t * 256;                 // 2048 x 16B
            int row = i >> 4, c = i & 15;
            *(uint4*)(smem + SM_A + row * APITCH + c * 16) = src[i];
        }
    }
    __syncthreads();

    // ---- hoist A fragments to registers (loop-invariant for whole CTA) ----
    uint32_t a_frag[8][2][4];
    {
        uint32_t aBase0 = sbase + SM_A +
            (uint32_t)(warp_n * 32 + (lane & 15)) * APITCH + (uint32_t)(lane >> 4) * 16;
#pragma unroll
        for (int ks = 0; ks < 8; ks++) {
            ldmatrix_x4(a_frag[ks][0], aBase0 + ks * 32);
            ldmatrix_x4(a_frag[ks][1], aBase0 + 16 * APITCH + ks * 32);
        }
    }

    // B ldmatrix per-lane base (view 0; other views add v*BVIEW)
    const uint32_t bBase0 = sbase + SM_B +
        (uint32_t)(warp_m * 32 + ((lane >> 4) << 3) + (lane & 7)) * APITCH +
        (uint32_t)((lane >> 3) & 1) * 16;

    float accv[NVIEWS][4];
#pragma unroll
    for (int v = 0; v < NVIEWS; v++)
#pragma unroll
        for (int r = 0; r < 4; r++) accv[v][r] = 0.0f;

    for (int mt = 0; mt < TPC; mt++) {
        const int m0 = m_base + mt * TILE_M;
        __syncthreads();   // all warps done with tile mt-1 (B + both S buffers safe)

        if (mt + 1 < TPC) {    // prefetch next S tile
            const float* src = S + (size_t)n0 * NROWS + (m0 + TILE_M);
            uint32_t dstb = sbase + SM_S + (uint32_t)((mt + 1) & 1) * SBUF;
#pragma unroll
            for (int t = 0; t < 8; t++) {
                int i = tid + t * 256;
                int row = i >> 4, c = i & 15;
                cp_async16(dstb + row * SPITCHB + c * 16,
                           src + (size_t)row * NROWS + c * 4);
            }
            CP_COMMIT();
        }

        // stage B tiles for ALL 3 views (64 rows x 128 bf16 each)
        {
#pragma unroll
            for (int t = 0; t < 12; t++) {
                int i = tid + t * 256;             // 3072 x 16B
                int view = i >> 10, r = (i >> 4) & 63, c = i & 15;
                const uint4* src = (const uint4*)(g_B +
                    ((size_t)view * NROWS + m0 + r) * DDIM);
                *(uint4*)(smem + SM_B + view * BVIEW + r * APITCH + c * 16) = src[c];
            }
        }
        if (mt + 1 < TPC) CP_WAIT(1); else CP_WAIT(0);
        __syncthreads();   // B staged + S(mt) visible

        const float* sS = (const float*)(smem + SM_S + (size_t)(mt & 1) * SBUF);

#pragma unroll
        for (int v = 0; v < NVIEWS; v++) {
            // ---- 128x64x128 bf16 GEMM, register accumulators ----
            float acc[2][4][4];
#pragma unroll
            for (int fi = 0; fi < 2; fi++)
#pragma unroll
                for (int mi = 0; mi < 4; mi++)
#pragma unroll
                    for (int r = 0; r < 4; r++) acc[fi][mi][r] = 0.0f;

            const uint32_t bV = bBase0 + (uint32_t)v * BVIEW;
#pragma unroll
            for (int ks = 0; ks < 8; ks++) {
                uint32_t b[2][4];
                ldmatrix_x4(b[0], bV + ks * 32);
                ldmatrix_x4(b[1], bV + 16 * APITCH + ks * 32);
#pragma unroll
                for (int fi = 0; fi < 2; fi++)
#pragma unroll
                    for (int bp = 0; bp < 2; bp++)
#pragma unroll
                        for (int t2 = 0; t2 < 2; t2++)
                            mma_16816(acc[fi][bp * 2 + t2], a_frag[ks][fi],
                                      b[bp][2 * t2], b[bp][2 * t2 + 1]);
            }

            // ---- fused epilogue: accv += (1 - S) * exp(sim / 0.5) ----
#pragma unroll
            for (int fi = 0; fi < 2; fi++) {
                const float* pA = sS +
                    (size_t)(warp_n * 32 + fi * 16 + (lane >> 2)) * SPITCHW +
                    warp_m * 32 + 2 * (lane & 3);
                const float* pB = pA + 8 * SPITCHW;
                float sA = 0.0f, sB = 0.0f;
#pragma unroll
                for (int mi = 0; mi < 4; mi++) {
                    float2 wA = *(const float2*)(pA + mi * 8);
                    float2 wB = *(const float2*)(pB + mi * 8);
                    const float* d = acc[fi][mi];
                    sA += (1.0f - wA.x) * __expf(2.0f * d[0]) +
                          (1.0f - wA.y) * __expf(2.0f * d[1]);
                    sB += (1.0f - wB.x) * __expf(2.0f * d[2]) +
                          (1.0f - wB.y) * __expf(2.0f * d[3]);
                }
                accv[v][fi * 2 + 0] += sA;
                accv[v][fi * 2 + 1] += sB;
            }
        }
    }

    // ---- quad-reduce, write partial denominators ----
#pragma unroll
    for (int v = 0; v < NVIEWS; v++)
#pragma unroll
        for (int r = 0; r < 4; r++) {
            float val = accv[v][r];
            val += __shfl_xor_sync(0xFFFFFFFFu, val, 1);
            val += __shfl_xor_sync(0xFFFFFFFFu, val, 2);
            if ((lane & 3) == 0) {
                int nl = warp_n * 32 + (r >> 1) * 16 + (lane >> 2) + (r & 1) * 8;
                g_partial[((chunk * 2 + warp_m) * NVIEWS + v) * NROWS + n0 + nl] = val;
            }
        }
}

// ============================ kernel 3: positive + loss + block partials ===
__global__ __launch_bounds__(256) void posloss_kernel() {
    __shared__ float sm[256];
    int idx = blockIdx.x * 256 + threadIdx.x;      // < 24576
    int v = idx / NROWS, n = idx % NROWS;

    const uint4* pa = (const uint4*)(g_A + (size_t)n * DDIM);
    const uint4* pb = (const uint4*)(g_B + ((size_t)v * NROWS + n) * DDIM);
    float d = 0.f;
#pragma unroll
    for (int i = 0; i < 16; i++) {
        uint4 ua = pa[i], ub = pb[i];
        const __nv_bfloat162* xa = (const __nv_bfloat162*)&ua;
        const __nv_bfloat162* xb = (const __nv_bfloat162*)&ub;
#pragma unroll
        for (int j = 0; j < 4; j++) {
            float2 a = __bfloat1622float2(xa[j]);
            float2 b = __bfloat1622float2(xb[j]);
            d += a.x * b.x + a.y * b.y;
        }
    }
    float denom = 0.f;
#pragma unroll
    for (int p = 0; p < NSLOT; p++)
        denom += g_partial[(p * NVIEWS + v) * NROWS + n];
    denom = fmaxf(denom, 1e-9f);
    float loss = logf(denom) - 2.0f * d;           // -(pos - log denom)

    sm[threadIdx.x] = loss;
    __syncthreads();
#pragma unroll
    for (int st = 128; st; st >>= 1) {
        if (threadIdx.x < st) sm[threadIdx.x] += sm[threadIdx.x + st];
        __syncthreads();
    }
    if (threadIdx.x == 0) g_bsum[blockIdx.x] = sm[0];
}

// ============================ kernel 4: final tiny reduce ==================
__global__ void final_reduce(float* __restrict__ out) {
    int lane = threadIdx.x;
    float s = 0.f;
    for (int i = lane; i < 96; i += 32) s += g_bsum[i];
#pragma unroll
    for (int o = 16; o; o >>= 1) s += __shfl_xor_sync(0xFFFFFFFFu, s, o);
    if (lane == 0) out[0] = s * (1.0f / (NVIEWS * NROWS));
}

// ============================ launch =======================================
extern "C" void kernel_launch(void* const* d_in, const int* in_sizes, int n_in,
                              void* d_out, int out_size) {
    const float* Hc = (const float*)d_in[0];
    const float* S  = (const float*)d_in[1];
    const float* Hv = (const float*)d_in[2];

    cudaFuncSetAttribute(sgcl_main, cudaFuncAttributeMaxDynamicSharedMemorySize,
                         SMEM_BYTES);

    prof_pad1<<<1, 32>>>();
    prof_pad2<<<1, 32>>>();
    normalize_kernel<<<(4 * NROWS) / 8, 256>>>(Hc, Hv);
    sgcl_main<<<dim3(NCHUNK, NROWS / TILE_N), 256, SMEM_BYTES>>>(S);
    posloss_kernel<<<96, 256>>>();
    final_reduce<<<1, 32>>>((float*)d_out);
}